// round 7
// baseline (speedup 1.0000x reference)
#include <cuda_runtime.h>
#include <math.h>

#define NMAX 100000
#define EMAX 1600000

// ---------------- scratch ----------------
__device__ __align__(16) float g_bufA[NMAX * 64];   // h
__device__ __align__(16) float g_bufB[NMAX * 64];   // g = (h@W)*dinv
__device__ float g_dinv[NMAX];
__device__ int   g_cnt[NMAX];
__device__ int   g_rowptr[NMAX + 1];
__device__ int   g_fill[NMAX];
__device__ int   g_col[EMAX];
__device__ int   g_src[EMAX];
__device__ int   g_dst[EMAX];
__device__ int   g_idx64;
__device__ int   g_bsum[128];
__device__ int   g_boff[128];

// ---------------- edge-index dtype detection + conversion (+count) ---------
__global__ void k_detect(const unsigned* __restrict__ w, int e) {
    __shared__ int nonzero;
    if (threadIdx.x == 0) nonzero = 0;
    __syncthreads();
    int i = threadIdx.x;
    if (2 * i + 1 < 2 * e) {
        if (w[2 * i + 1] != 0u) atomicAdd(&nonzero, 1);
    }
    __syncthreads();
    if (threadIdx.x == 0) g_idx64 = (nonzero == 0) ? 1 : 0;
}

__global__ void k_convert(const void* __restrict__ ei, int e, int n) {
    int i = blockIdx.x * blockDim.x + threadIdx.x;
    if (i >= e) return;
    long long s, d;
    if (g_idx64) {
        const long long* p = (const long long*)ei;
        s = p[i]; d = p[(size_t)e + i];
    } else {
        const int* p = (const int*)ei;
        s = p[i]; d = p[(size_t)e + i];
    }
    int si = (s >= 0 && s < n) ? (int)s : 0;
    int di = (d >= 0 && d < n) ? (int)d : 0;
    g_src[i] = si;
    g_dst[i] = di;
    atomicAdd(&g_cnt[di], 1);
}

// ---------------- 3-phase scan + finalize (dinv, fill init) -----------------
__global__ void k_scan1(int n) {
    __shared__ int ws[32];
    int i = blockIdx.x * 1024 + threadIdx.x;
    int lane = threadIdx.x & 31, wid = threadIdx.x >> 5;
    int v = (i < n) ? g_cnt[i] : 0;
    int x = v;
    #pragma unroll
    for (int d = 1; d < 32; d <<= 1) {
        int t = __shfl_up_sync(0xffffffffu, x, d);
        if (lane >= d) x += t;
    }
    if (lane == 31) ws[wid] = x;
    __syncthreads();
    if (wid == 0) {
        int s = ws[lane];
        #pragma unroll
        for (int d = 1; d < 32; d <<= 1) {
            int t = __shfl_up_sync(0xffffffffu, s, d);
            if (lane >= d) s += t;
        }
        ws[lane] = s;
    }
    __syncthreads();
    int incl = x + (wid ? ws[wid - 1] : 0);
    if (i < n) g_rowptr[i + 1] = incl;
    if (threadIdx.x == 1023) g_bsum[blockIdx.x] = incl;
}

__global__ void k_scan2(int nb) {
    __shared__ int sm[128];
    int t = threadIdx.x;
    int v = (t < nb) ? g_bsum[t] : 0;
    sm[t] = v;
    __syncthreads();
    #pragma unroll
    for (int d = 1; d < 128; d <<= 1) {
        int a = (t >= d) ? sm[t - d] : 0;
        __syncthreads();
        sm[t] += a;
        __syncthreads();
    }
    g_boff[t] = sm[t] - v;   // exclusive
}

__global__ void k_scan3(int n) {
    int i = blockIdx.x * 1024 + threadIdx.x;
    if (i >= n) return;
    int boff = g_boff[blockIdx.x];
    int v = g_rowptr[i + 1] + boff;
    g_rowptr[i + 1] = v;
    int c = g_cnt[i];
    g_fill[i] = v - c;
    g_dinv[i] = rsqrtf((float)(c + 1));
    if (i == 0) g_rowptr[0] = 0;
}

__global__ void k_fill(int e) {
    int i = blockIdx.x * blockDim.x + threadIdx.x;
    if (i < e) {
        int pos = atomicAdd(&g_fill[g_dst[i]], 1);
        if (pos >= 0 && pos < EMAX) g_col[pos] = g_src[i];
    }
}

// ---------------- tf32 helpers ----------------------------------------------
__device__ __forceinline__ unsigned f2tf32(float x) {
    unsigned r;
    asm("cvt.rna.tf32.f32 %0, %1;" : "=r"(r) : "f"(x));
    return r;
}
__device__ __forceinline__ void mma_tf32(float* d, const unsigned* a,
                                         unsigned b0, unsigned b1) {
    asm volatile(
        "mma.sync.aligned.m16n8k8.row.col.f32.tf32.tf32.f32 "
        "{%0,%1,%2,%3}, {%4,%5,%6,%7}, {%8,%9}, {%0,%1,%2,%3};"
        : "+f"(d[0]), "+f"(d[1]), "+f"(d[2]), "+f"(d[3])
        : "r"(a[0]), "r"(a[1]), "r"(a[2]), "r"(a[3]), "r"(b0), "r"(b1));
}

// ---------------- GEMM (tensor core, 3xTF32): out = in @ W (+b | *dinv) -----
// NWARP warps, each owns 16 node-rows; k-chunks of 8; NT = FOUT/8 n-tiles.
// Xs: [NODES][RS] fp32 row-major. Whi/Wlo: [FOUT][RS] = W transposed + split.
// Fragment LDS banks: (4*gid + tig) mod 32 -> conflict-free for RS%32==4.
template<int FIN, int FOUT, bool PRE, int NODES, int NWARP>
__launch_bounds__(NWARP * 32)
__global__ void k_gemm_tc(const float* __restrict__ X, const float* __restrict__ W,
                          const float* __restrict__ b, int n)
{
    constexpr int RS = FIN + 4;
    constexpr int NT = FOUT / 8;
    constexpr int T  = NWARP * 32;
    extern __shared__ float sm[];
    float* Xs  = sm;                    // [NODES][RS]
    float* Whi = sm + NODES * RS;       // [FOUT][RS]
    float* Wlo = Whi + FOUT * RS;

    const float* __restrict__ in = PRE ? X : g_bufA;
    float* __restrict__ out = PRE ? g_bufA : g_bufB;

    int tid = threadIdx.x;
    int node0 = blockIdx.x * NODES;

    // stage X (fp32, float4, zero-padded tail)
    for (int i = tid; i < NODES * FIN / 4; i += T) {
        int row = (i * 4) / FIN;
        int col = (i * 4) % FIN;
        int nd = node0 + row;
        float4 v = (nd < n) ? *(const float4*)&in[(size_t)nd * FIN + col]
                            : make_float4(0.f, 0.f, 0.f, 0.f);
        *(float4*)&Xs[row * RS + col] = v;
    }
    // stage W: transpose + tf32 hi/lo split
    for (int i = tid; i < FIN * FOUT; i += T) {
        int k = i / FOUT, f = i % FOUT;
        float w = W[i];
        unsigned hb = f2tf32(w);
        float hf = __uint_as_float(hb);
        unsigned lb = f2tf32(w - hf);
        Whi[f * RS + k] = hf;
        Wlo[f * RS + k] = __uint_as_float(lb);
    }
    __syncthreads();

    int w = tid >> 5, lane = tid & 31;
    int gid = lane >> 2, tig = lane & 3;

    float acc[NT][4];
    #pragma unroll
    for (int t = 0; t < NT; t++)
        #pragma unroll
        for (int j = 0; j < 4; j++) acc[t][j] = 0.f;

    const float* xr0 = Xs + (w * 16 + gid) * RS;   // rows gid / gid+8 of m-tile
    const float* xr1 = xr0 + 8 * RS;

    #pragma unroll
    for (int kc = 0; kc < FIN; kc += 8) {
        float af[4];
        af[0] = xr0[kc + tig];
        af[1] = xr1[kc + tig];
        af[2] = xr0[kc + tig + 4];
        af[3] = xr1[kc + tig + 4];
        unsigned ah[4], al[4];
        #pragma unroll
        for (int j = 0; j < 4; j++) {
            ah[j] = f2tf32(af[j]);
            al[j] = f2tf32(af[j] - __uint_as_float(ah[j]));
        }
        #pragma unroll
        for (int t = 0; t < NT; t++) {
            const float* wh = Whi + (t * 8 + gid) * RS + kc + tig;
            const float* wl = Wlo + (t * 8 + gid) * RS + kc + tig;
            unsigned b0h = __float_as_uint(wh[0]);
            unsigned b1h = __float_as_uint(wh[4]);
            unsigned b0l = __float_as_uint(wl[0]);
            unsigned b1l = __float_as_uint(wl[4]);
            mma_tf32(acc[t], al, b0h, b1h);   // Alo * Bhi
            mma_tf32(acc[t], ah, b0l, b1l);   // Ahi * Blo
            mma_tf32(acc[t], ah, b0h, b1h);   // Ahi * Bhi
        }
    }

    // epilogue: c0,c1 -> (row, col=2tig, 2tig+1); c2,c3 -> row+8
    int r0 = node0 + w * 16 + gid;
    int r1 = r0 + 8;
    float s0 = 1.f, s1 = 1.f;
    if (!PRE) {
        if (r0 < n) s0 = g_dinv[r0];
        if (r1 < n) s1 = g_dinv[r1];
    }
    #pragma unroll
    for (int t = 0; t < NT; t++) {
        int col = t * 8 + 2 * tig;
        float2 bb = make_float2(0.f, 0.f);
        if (PRE) bb = *(const float2*)&b[col];
        if (r0 < n) {
            float2 v;
            v.x = PRE ? (acc[t][0] + bb.x) : (acc[t][0] * s0);
            v.y = PRE ? (acc[t][1] + bb.y) : (acc[t][1] * s0);
            *(float2*)&out[(size_t)r0 * FOUT + col] = v;
        }
        if (r1 < n) {
            float2 v;
            v.x = PRE ? (acc[t][2] + bb.x) : (acc[t][2] * s1);
            v.y = PRE ? (acc[t][3] + bb.y) : (acc[t][3] * s1);
            *(float2*)&out[(size_t)r1 * FOUT + col] = v;
        }
    }
}

// ---------------- aggregation (unchanged, measured-good) --------------------
template<int FOUT, bool RELU, bool NORM, bool TO_OUT>
__global__ void k_agg(const float* __restrict__ bias, float* __restrict__ Y, int n)
{
    constexpr int LPG = FOUT / 4;
    constexpr int NG = 32 / LPG;
    int node = (int)((blockIdx.x * blockDim.x + threadIdx.x) >> 5);
    if (node >= n) return;
    int lane = threadIdx.x & 31;
    int g = lane / LPG;
    int fl = lane % LPG;
    const float* __restrict__ G = g_bufB;
    float* __restrict__ O = TO_OUT ? Y : g_bufA;

    float4 acc = make_float4(0.f, 0.f, 0.f, 0.f);
    if (g == 0) acc = *(const float4*)(G + (size_t)node * FOUT + fl * 4);  // self

    int s = g_rowptr[node], e = g_rowptr[node + 1];
    int j = s + g;
    for (; j + NG < e; j += 2 * NG) {
        int c0 = g_col[j];
        int c1 = g_col[j + NG];
        float4 v0 = *(const float4*)(G + (size_t)c0 * FOUT + fl * 4);
        float4 v1 = *(const float4*)(G + (size_t)c1 * FOUT + fl * 4);
        acc.x += v0.x + v1.x;
        acc.y += v0.y + v1.y;
        acc.z += v0.z + v1.z;
        acc.w += v0.w + v1.w;
    }
    if (j < e) {
        int c0 = g_col[j];
        float4 v0 = *(const float4*)(G + (size_t)c0 * FOUT + fl * 4);
        acc.x += v0.x; acc.y += v0.y; acc.z += v0.z; acc.w += v0.w;
    }

    #pragma unroll
    for (int d = LPG; d < 32; d <<= 1) {
        acc.x += __shfl_xor_sync(0xffffffffu, acc.x, d);
        acc.y += __shfl_xor_sync(0xffffffffu, acc.y, d);
        acc.z += __shfl_xor_sync(0xffffffffu, acc.z, d);
        acc.w += __shfl_xor_sync(0xffffffffu, acc.w, d);
    }

    float di = g_dinv[node];
    float4 bv = *(const float4*)(bias + fl * 4);
    float4 v;
    v.x = di * acc.x + bv.x;
    v.y = di * acc.y + bv.y;
    v.z = di * acc.z + bv.z;
    v.w = di * acc.w + bv.w;
    if (RELU) {
        v.x = fmaxf(v.x, 0.f); v.y = fmaxf(v.y, 0.f);
        v.z = fmaxf(v.z, 0.f); v.w = fmaxf(v.w, 0.f);
    }
    if (NORM) {
        float ss = v.x * v.x + v.y * v.y + v.z * v.z + v.w * v.w;
        #pragma unroll
        for (int d = 1; d < LPG; d <<= 1) ss += __shfl_xor_sync(0xffffffffu, ss, d);
        float inv = 1.0f / fmaxf(sqrtf(ss), 1e-12f);
        v.x *= inv; v.y *= inv; v.z *= inv; v.w *= inv;
    }
    if (g == 0) *(float4*)(O + (size_t)node * FOUT + fl * 4) = v;
}

// ---------------- host ----------------
extern "C" void kernel_launch(void* const* d_in, const int* in_sizes, int n_in,
                              void* d_out, int out_size)
{
    const float* x     = (const float*)d_in[0];
    const void*  ei    = d_in[1];
    const float* W_pre = (const float*)d_in[2];
    const float* b_pre = (const float*)d_in[3];
    const float* W1    = (const float*)d_in[4];
    const float* b1    = (const float*)d_in[5];
    const float* W2    = (const float*)d_in[6];
    const float* b2    = (const float*)d_in[7];
    const float* W3    = (const float*)d_in[8];
    const float* b3    = (const float*)d_in[9];
    float*       out   = (float*)d_out;

    int n = in_sizes[0] / 128;
    int e = in_sizes[1] / 2;
    int eb = (e + 255) / 256;
    int sb = (n + 1023) / 1024;

    // smem: Xs[NODES*(FIN+4)] + Whi/Wlo[FOUT*(FIN+4)]*2
    // pre:  <128,64,...,64,4>  : (64*132 + 2*64*132)*4  = 101376
    // mid:  <64,64,...,128,8>  : (128*68 + 2*64*68)*4   = 69632
    // out:  <64,32,...,128,8>  : (128*68 + 2*32*68)*4   = 52224
    const int smem_pre = (64 * 132 + 2 * 64 * 132) * 4;
    const int smem_mid = (128 * 68 + 2 * 64 * 68) * 4;
    const int smem_out = (128 * 68 + 2 * 32 * 68) * 4;
    cudaFuncSetAttribute(k_gemm_tc<128, 64, true, 64, 4>,
                         cudaFuncAttributeMaxDynamicSharedMemorySize, smem_pre);
    cudaFuncSetAttribute(k_gemm_tc<64, 64, false, 128, 8>,
                         cudaFuncAttributeMaxDynamicSharedMemorySize, smem_mid);
    cudaFuncSetAttribute(k_gemm_tc<64, 32, false, 128, 8>,
                         cudaFuncAttributeMaxDynamicSharedMemorySize, smem_out);

    int gb64  = (n + 63) / 64;    // 1563
    int gb128 = (n + 127) / 128;  // 782
    int ab    = (n + 7) / 8;

    // CSR build; pre-GEMM at launch slot 5 for the ncu window (-s 5 -c 1).
    void* cntp = nullptr;
    cudaGetSymbolAddress(&cntp, g_cnt);
    cudaMemsetAsync(cntp, 0, (size_t)n * sizeof(int));                    // 1
    k_detect<<<1, 256>>>((const unsigned*)ei, e);                         // 2
    k_convert<<<eb, 256>>>(ei, e, n);                                     // 3
    k_scan1<<<sb, 1024>>>(n);                                             // 4
    // pre: h0 = x @ W_pre + b_pre -> bufA                                // 5 (profiled)
    k_gemm_tc<128, 64, true, 64, 4><<<gb64, 128, smem_pre>>>(x, W_pre, b_pre, n);
    k_scan2<<<1, 128>>>(sb);                                              // 6
    k_scan3<<<sb, 1024>>>(n);                                             // 7
    k_fill<<<eb, 256>>>(e);                                               // 8

    // layer 1
    k_gemm_tc<64, 64, false, 128, 8><<<gb128, 256, smem_mid>>>(x, W1, b1, n);
    k_agg<64, true, false, false><<<ab, 256>>>(b1, out, n);
    // layer 2
    k_gemm_tc<64, 64, false, 128, 8><<<gb128, 256, smem_mid>>>(x, W2, b2, n);
    k_agg<64, true, false, false><<<ab, 256>>>(b2, out, n);
    // layer 3 + L2 normalize
    k_gemm_tc<64, 32, false, 128, 8><<<gb128, 256, smem_out>>>(x, W3, b3, n);
    k_agg<32, false, true, true><<<ab, 256>>>(b3, out, n);
}

// round 9
// speedup vs baseline: 1.1196x; 1.1196x over previous
#include <cuda_runtime.h>
#include <math.h>

#define NMAX 100000
#define EMAX 1600000

// ---------------- scratch ----------------
__device__ __align__(16) float g_bufA[NMAX * 64];   // h (post-activation)
__device__ __align__(16) float g_bufB[NMAX * 64];   // g = (h@W)*dinv
__device__ __align__(16) float g_W12[128 * 64];     // W_pre @ W1
__device__ __align__(16) float g_b12[64];           // b_pre @ W1
__device__ float g_dinv[NMAX];
__device__ int   g_cnt[NMAX];
__device__ int   g_rowptr[NMAX + 1];
__device__ int   g_fill[NMAX];
__device__ int   g_col[EMAX];
__device__ int   g_bsum[128];

// ------------- launch 1: zero counters + (block 0) W12 = W_pre@W1 -----------
__global__ void k_w12zero(const float* __restrict__ Wpre,
                          const float* __restrict__ b_pre,
                          const float* __restrict__ W1, int n)
{
    int i = blockIdx.x * 1024 + threadIdx.x;
    if (i < n) g_cnt[i] = 0;
    if (blockIdx.x == 0) {
        __shared__ float W1s[64 * 64];
        for (int t = threadIdx.x; t < 64 * 64; t += 1024) W1s[t] = W1[t];
        __syncthreads();
        for (int idx = threadIdx.x; idx < 128 * 64; idx += 1024) {
            int k = idx >> 6, f = idx & 63;
            float s = 0.f;
            #pragma unroll 8
            for (int j = 0; j < 64; j++) s += Wpre[k * 64 + j] * W1s[j * 64 + f];
            g_W12[idx] = s;
        }
        if (threadIdx.x < 64) {
            int f = threadIdx.x;
            float s = 0.f;
            #pragma unroll 8
            for (int j = 0; j < 64; j++) s += b_pre[j] * W1s[j * 64 + f];
            g_b12[f] = s;
        }
    }
}

// ------------- launch 2: in-degree count (dtype vote per block) --------------
// int64 values < 2^31 have all-zero odd 32-bit words (sampled on src half,
// which is in-bounds under both interpretations).
__global__ void k_count(const void* __restrict__ ei, int e, int n) {
    int i = blockIdx.x * blockDim.x + threadIdx.x;
    const unsigned* w = (const unsigned*)ei;
    int odd = (i < e) ? (w[2 * i + 1] != 0u) : 0;
    int is32 = __syncthreads_or(odd);
    if (i >= e) return;
    long long d = is32 ? (long long)((const int*)ei)[(size_t)e + i]
                       : ((const long long*)ei)[(size_t)e + i];
    int di = (d >= 0 && d < n) ? (int)d : 0;
    atomicAdd(&g_cnt[di], 1);
}

// ------------- launch 3: per-block inclusive scan ----------------------------
__global__ void k_scan1(int n) {
    __shared__ int ws[32];
    int i = blockIdx.x * 1024 + threadIdx.x;
    int lane = threadIdx.x & 31, wid = threadIdx.x >> 5;
    int v = (i < n) ? g_cnt[i] : 0;
    int x = v;
    #pragma unroll
    for (int d = 1; d < 32; d <<= 1) {
        int t = __shfl_up_sync(0xffffffffu, x, d);
        if (lane >= d) x += t;
    }
    if (lane == 31) ws[wid] = x;
    __syncthreads();
    if (wid == 0) {
        int s = ws[lane];
        #pragma unroll
        for (int d = 1; d < 32; d <<= 1) {
            int t = __shfl_up_sync(0xffffffffu, s, d);
            if (lane >= d) s += t;
        }
        ws[lane] = s;
    }
    __syncthreads();
    int incl = x + (wid ? ws[wid - 1] : 0);
    if (i < n) g_rowptr[i + 1] = incl;
    if (threadIdx.x == 1023) g_bsum[blockIdx.x] = incl;
}

// ------------- launch 4: block offsets inline + finalize ---------------------
__global__ void k_scan3(int n) {
    __shared__ int boff_sh;
    if (threadIdx.x < 32) {
        int ssum = 0;
        for (int k = threadIdx.x; k < blockIdx.x; k += 32) ssum += g_bsum[k];
        #pragma unroll
        for (int d = 16; d; d >>= 1) ssum += __shfl_xor_sync(0xffffffffu, ssum, d);
        if (threadIdx.x == 0) boff_sh = ssum;
    }
    __syncthreads();
    int i = blockIdx.x * 1024 + threadIdx.x;
    if (i >= n) return;
    int v = g_rowptr[i + 1] + boff_sh;
    g_rowptr[i + 1] = v;
    int c = g_cnt[i];
    g_fill[i] = v - c;
    g_dinv[i] = rsqrtf((float)(c + 1));
    if (i == 0) g_rowptr[0] = 0;
}

// ------------- launch 6: CSR fill (re-decodes edges, dtype vote) -------------
__global__ void k_fill(const void* __restrict__ ei, int e, int n) {
    int i = blockIdx.x * blockDim.x + threadIdx.x;
    const unsigned* w = (const unsigned*)ei;
    int odd = (i < e) ? (w[2 * i + 1] != 0u) : 0;
    int is32 = __syncthreads_or(odd);
    if (i >= e) return;
    long long s, d;
    if (is32) {
        const int* p = (const int*)ei;
        s = p[i]; d = p[(size_t)e + i];
    } else {
        const long long* p = (const long long*)ei;
        s = p[i]; d = p[(size_t)e + i];
    }
    int si = (s >= 0 && s < n) ? (int)s : 0;
    int di = (d >= 0 && d < n) ? (int)d : 0;
    int pos = atomicAdd(&g_fill[di], 1);
    if (pos >= 0 && pos < EMAX) g_col[pos] = si;
}

// ---------------- GEMM: g_bufB = (in @ W [+ b]) * dinv ----------------------
// 256 threads. FT f-threads x NT node-threads; 4x4 register tile per thread.
// f = fx + FT*j (interleaved -> conflict-free Wt reads).
template<int FIN, int FOUT, bool BIAS, int NODES, int FT>
__launch_bounds__(256)
__global__ void k_gemm(const float* __restrict__ in, const float* __restrict__ W,
                       const float* __restrict__ b, int n)
{
    constexpr int NT = 256 / FT;
    constexpr int RS = FIN + 4;
    extern __shared__ float sm[];
    float* Wt = sm;               // [FOUT][RS]  (transposed W)
    float* Xs = sm + FOUT * RS;   // [NODES][RS]

    float* __restrict__ out = g_bufB;

    int tid = threadIdx.x;
    for (int i = tid; i < FIN * FOUT; i += 256) {
        int k = i / FOUT, f = i % FOUT;
        Wt[f * RS + k] = W[i];
    }
    int node0 = blockIdx.x * NODES;
    for (int i = tid; i < NODES * FIN / 4; i += 256) {
        int row = (i * 4) / FIN;
        int col = (i * 4) % FIN;
        int nd = node0 + row;
        float4 v = (nd < n) ? *(const float4*)&in[(size_t)nd * FIN + col]
                            : make_float4(0.f, 0.f, 0.f, 0.f);
        *(float4*)&Xs[row * RS + col] = v;
    }
    __syncthreads();

    int fx = tid % FT;
    int nx = tid / FT;
    float acc[4][4];
    #pragma unroll
    for (int i = 0; i < 4; i++)
        #pragma unroll
        for (int j = 0; j < 4; j++) acc[i][j] = 0.f;

    const float* xb = Xs + nx * RS;
    const float* wb = Wt + fx * RS;
    #pragma unroll
    for (int k = 0; k < FIN; k += 4) {
        float4 xv[4], wv[4];
        #pragma unroll
        for (int i = 0; i < 4; i++) xv[i] = *(const float4*)(xb + i * NT * RS + k);
        #pragma unroll
        for (int j = 0; j < 4; j++) wv[j] = *(const float4*)(wb + j * FT * RS + k);
        #pragma unroll
        for (int i = 0; i < 4; i++)
            #pragma unroll
            for (int j = 0; j < 4; j++) {
                acc[i][j] += xv[i].x * wv[j].x;
                acc[i][j] += xv[i].y * wv[j].y;
                acc[i][j] += xv[i].z * wv[j].z;
                acc[i][j] += xv[i].w * wv[j].w;
            }
    }

    #pragma unroll
    for (int i = 0; i < 4; i++) {
        int nd = node0 + nx + NT * i;
        if (nd < n) {
            float scale = g_dinv[nd];
            #pragma unroll
            for (int j = 0; j < 4; j++) {
                int f = fx + FT * j;
                float v = acc[i][j];
                if (BIAS) v += b[f];
                v *= scale;
                out[(size_t)nd * FOUT + f] = v;
            }
        }
    }
}

// ---------------- aggregation (measured-good R6 version) --------------------
template<int FOUT, bool RELU, bool NORM, bool TO_OUT>
__global__ void k_agg(const float* __restrict__ bias, float* __restrict__ Y, int n)
{
    constexpr int LPG = FOUT / 4;
    constexpr int NG = 32 / LPG;
    int node = (int)((blockIdx.x * blockDim.x + threadIdx.x) >> 5);
    if (node >= n) return;
    int lane = threadIdx.x & 31;
    int g = lane / LPG;
    int fl = lane % LPG;
    const float* __restrict__ G = g_bufB;
    float* __restrict__ O = TO_OUT ? Y : g_bufA;

    float4 acc = make_float4(0.f, 0.f, 0.f, 0.f);
    if (g == 0) acc = *(const float4*)(G + (size_t)node * FOUT + fl * 4);  // self

    int s = g_rowptr[node], e = g_rowptr[node + 1];
    int j = s + g;
    for (; j + NG < e; j += 2 * NG) {
        int c0 = g_col[j];
        int c1 = g_col[j + NG];
        float4 v0 = *(const float4*)(G + (size_t)c0 * FOUT + fl * 4);
        float4 v1 = *(const float4*)(G + (size_t)c1 * FOUT + fl * 4);
        acc.x += v0.x + v1.x;
        acc.y += v0.y + v1.y;
        acc.z += v0.z + v1.z;
        acc.w += v0.w + v1.w;
    }
    if (j < e) {
        int c0 = g_col[j];
        float4 v0 = *(const float4*)(G + (size_t)c0 * FOUT + fl * 4);
        acc.x += v0.x; acc.y += v0.y; acc.z += v0.z; acc.w += v0.w;
    }

    #pragma unroll
    for (int d = LPG; d < 32; d <<= 1) {
        acc.x += __shfl_xor_sync(0xffffffffu, acc.x, d);
        acc.y += __shfl_xor_sync(0xffffffffu, acc.y, d);
        acc.z += __shfl_xor_sync(0xffffffffu, acc.z, d);
        acc.w += __shfl_xor_sync(0xffffffffu, acc.w, d);
    }

    float di = g_dinv[node];
    float4 bv = *(const float4*)(bias + fl * 4);
    float4 v;
    v.x = di * acc.x + bv.x;
    v.y = di * acc.y + bv.y;
    v.z = di * acc.z + bv.z;
    v.w = di * acc.w + bv.w;
    if (RELU) {
        v.x = fmaxf(v.x, 0.f); v.y = fmaxf(v.y, 0.f);
        v.z = fmaxf(v.z, 0.f); v.w = fmaxf(v.w, 0.f);
    }
    if (NORM) {
        float ss = v.x * v.x + v.y * v.y + v.z * v.z + v.w * v.w;
        #pragma unroll
        for (int d = 1; d < LPG; d <<= 1) ss += __shfl_xor_sync(0xffffffffu, ss, d);
        float inv = 1.0f / fmaxf(sqrtf(ss), 1e-12f);
        v.x *= inv; v.y *= inv; v.z *= inv; v.w *= inv;
    }
    if (g == 0) *(float4*)(O + (size_t)node * FOUT + fl * 4) = v;
}

// ---------------- host ----------------
extern "C" void kernel_launch(void* const* d_in, const int* in_sizes, int n_in,
                              void* d_out, int out_size)
{
    const float* x     = (const float*)d_in[0];
    const void*  ei    = d_in[1];
    const float* W_pre = (const float*)d_in[2];
    const float* b_pre = (const float*)d_in[3];
    const float* W1    = (const float*)d_in[4];
    const float* b1    = (const float*)d_in[5];
    const float* W2    = (const float*)d_in[6];
    const float* b2    = (const float*)d_in[7];
    const float* W3    = (const float*)d_in[8];
    const float* b3    = (const float*)d_in[9];
    float*       out   = (float*)d_out;

    int n = in_sizes[0] / 128;
    int e = in_sizes[1] / 2;
    int eb = (e + 255) / 256;
    int sb = (n + 1023) / 1024;

    const int smem_1 = (64 * (128 + 4) + 64 * (128 + 4)) * 4;   // 67584
    const int smem_2 = (64 * (64 + 4) + 64 * (64 + 4)) * 4;     // 34816
    const int smem_3 = (32 * (64 + 4) + 128 * (64 + 4)) * 4;    // 43520
    cudaFuncSetAttribute(k_gemm<128, 64, true, 64, 16>,
                         cudaFuncAttributeMaxDynamicSharedMemorySize, smem_1);
    cudaFuncSetAttribute(k_gemm<64, 64, false, 64, 16>,
                         cudaFuncAttributeMaxDynamicSharedMemorySize, smem_2);
    cudaFuncSetAttribute(k_gemm<64, 32, false, 128, 8>,
                         cudaFuncAttributeMaxDynamicSharedMemorySize, smem_3);

    void *w12p = nullptr, *b12p = nullptr, *bufAp = nullptr;
    cudaGetSymbolAddress(&w12p, g_W12);
    cudaGetSymbolAddress(&b12p, g_b12);
    cudaGetSymbolAddress(&bufAp, g_bufA);

    int gb64  = (n + 63) / 64;
    int gb128 = (n + 127) / 128;
    int ab    = (n + 7) / 8;

    // 1: zero counters + W12 = W_pre@W1 (block 0)
    k_w12zero<<<sb, 1024>>>(W_pre, b_pre, W1, n);
    // 2: in-degree count
    k_count<<<eb, 256>>>(ei, e, n);
    // 3-4: prefix scan + dinv/fill-init
    k_scan1<<<sb, 1024>>>(n);
    k_scan3<<<sb, 1024>>>(n);
    // 5 (profiled): fused layer-1 transform  bufB = (x @ W12 + b12) * dinv
    k_gemm<128, 64, true, 64, 16><<<gb64, 256, smem_1>>>(
        x, (const float*)w12p, (const float*)b12p, n);
    // 6: CSR fill
    k_fill<<<eb, 256>>>(ei, e, n);

    // layer 1 aggregate (+b1, relu) -> bufA
    k_agg<64, true, false, false><<<ab, 256>>>(b1, out, n);
    // layer 2
    k_gemm<64, 64, false, 64, 16><<<gb64, 256, smem_2>>>(
        (const float*)bufAp, W2, nullptr, n);
    k_agg<64, true, false, false><<<ab, 256>>>(b2, out, n);
    // layer 3 + L2 normalize
    k_gemm<64, 32, false, 128, 8><<<gb128, 256, smem_3>>>(
        (const float*)bufAp, W3, nullptr, n);
    k_agg<32, false, true, true><<<ab, 256>>>(b3, out, n);
}